// round 8
// baseline (speedup 1.0000x reference)
#include <cuda_runtime.h>
#include <math.h>

#define BATCH 1024
#define WARPS_PER_BLOCK 8
#define BLOCK (WARPS_PER_BLOCK * 32)
#define MAX_STEPS 128

// Grid tabulation of g(t1, tau): NG points, tau_j = (j-1)*h, h = t1/17
#define NG 20
#define NSEG 17

// Fast warp sum via integer redux (sm_80+; fp32 redux doesn't exist at this
// target). Fixed-point 2^-17 quantization through the float magic-number
// trick: ~42 cyc total vs ~130 for a 5-level shfl butterfly.
// Requires |sum(v)| < 32 (guaranteed: summands are tanh-bounded dot terms).
__device__ __forceinline__ float warp_sum(float v) {
    float biased = fmaf(v, 131072.0f, 12582912.0f);   // v*2^17 + 1.5*2^23
    int xi = __float_as_int(biased) - 0x4B400000;     // round(v*2^17)
    int s;
    asm("redux.sync.add.s32 %0, %1, 0xffffffff;" : "=r"(s) : "r"(xi));
    float fs = __int_as_float(s + 0x4B400000) - 12582912.0f;  // (float)s
    return fs * 7.62939453125e-06f;                   // * 2^-17
}

// Hardware MUFU tanh (sm_75+): ~16 cyc, max abs err ~5e-4
__device__ __forceinline__ float fast_tanh(float x) {
    float r;
    asm("tanh.approx.f32 %0, %1;" : "=f"(r) : "f"(x));
    return r;
}

// theta MLP layer2+3 (32-wide). pre = tW1a*tau + tb1 precomputed per lane.
__device__ __forceinline__ float theta_eval(float pre, float ys, float tbw,
                                            float tb2r, float tw3r,
                                            const float* __restrict__ sT2T,
                                            int lane) {
    float hv = fast_tanh(fmaf(tbw, ys, pre));
    float a[8];
    a[0] = tb2r;
    #pragma unroll
    for (int i = 1; i < 8; ++i) a[i] = 0.0f;
    #pragma unroll
    for (int k = 0; k < 32; k += 8) {
        float hb[8];
        #pragma unroll
        for (int i = 0; i < 8; ++i)
            hb[i] = __shfl_sync(0xffffffffu, hv, k + i);
        #pragma unroll
        for (int i = 0; i < 8; ++i)
            a[i] = fmaf(sT2T[(k + i) * 33 + lane], hb[i], a[i]);
    }
    float s01 = a[0] + a[1], s23 = a[2] + a[3];
    float s45 = a[4] + a[5], s67 = a[6] + a[7];
    float h2 = fast_tanh((s01 + s23) + (s45 + s67));
    return warp_sum(tw3r * h2);
}

// 4-point Lagrange cubic interpolation of g at tau.
__device__ __forceinline__ float g_interp(const float* __restrict__ sGw,
                                          float tau, float inv_h) {
    float s = fmaf(tau, inv_h, 1.0f);
    float fi = floorf(s);
    int i = (int)fi;
    i = i < 1 ? 1 : (i > NSEG ? NSEG : i);
    float u = s - (float)i;
    float p0 = sGw[i - 1], p1 = sGw[i], p2 = sGw[i + 1], p3 = sGw[i + 2];
    float um1 = u - 1.0f, um2 = u - 2.0f, up1 = u + 1.0f;
    float w0 = (-1.0f / 6.0f) * u * um1 * um2;
    float w1 = 0.5f * up1 * um1 * um2;
    float w2 = -0.5f * up1 * u * um2;
    float w3 = (1.0f / 6.0f) * up1 * u * um1;
    return fmaf(w0, p0, fmaf(w1, p1, fmaf(w2, p2, w3 * p3)));
}

// ---------------------------------------------------------------------------
// Single fused kernel: stage weights -> fold decoder -> per-warp g-grid
// tabulation -> adaptive Dopri5 loop with FSAL + cubic-interp phi.
// ---------------------------------------------------------------------------
__global__ void __launch_bounds__(BLOCK, 1)
neural_ode_kernel(const float* __restrict__ t,
                  const float* __restrict__ pW1, const float* __restrict__ pb1,
                  const float* __restrict__ pW2, const float* __restrict__ pb2,
                  const float* __restrict__ pW3, const float* __restrict__ pb3,
                  const float* __restrict__ dW, const float* __restrict__ db,
                  const float* __restrict__ tW1, const float* __restrict__ tb1,
                  const float* __restrict__ tW2, const float* __restrict__ tb2,
                  const float* __restrict__ tW3, const float* __restrict__ tb3,
                  float* __restrict__ out) {
    __shared__ float sW2T[64 * 65];   // pW2 transposed, padded (prologue only)
    __shared__ float sT2T[32 * 33];   // tW2 transposed, padded
    __shared__ float sW1a[64], sW1b[64], sPb1[64], sPb2[64], sw[64];
    __shared__ float sFoldP[4][64];   // cooperative fold partials
    __shared__ float sCp[64];
    __shared__ float sT1a[32], sT1b[32], sTb1[32], sTb2[32], sTw3[32];
    __shared__ float sScal[3];        // c_fold, db0, tb3_0
    __shared__ float sG[WARPS_PER_BLOCK][NG];

    int tid = threadIdx.x;
    for (int idx = tid; idx < 4096; idx += BLOCK) {
        int j = idx >> 6, k = idx & 63;
        sW2T[k * 65 + j] = pW2[idx];
    }
    for (int idx = tid; idx < 1024; idx += BLOCK) {
        int j = idx >> 5, k = idx & 31;
        sT2T[k * 33 + j] = tW2[idx];
    }
    // Cooperative decoder fold: w_j = sum_i dW[i]*pW3[i][j]  (4 partials/out)
    {
        int q = tid >> 6, j = tid & 63;
        float p = 0.0f;
        #pragma unroll
        for (int i = 0; i < 16; ++i)
            p = fmaf(dW[q * 16 + i], pW3[(q * 16 + i) * 64 + j], p);
        sFoldP[q][j] = p;
    }
    if (tid < 64) {
        sW1a[tid] = pW1[2 * tid];
        sW1b[tid] = pW1[2 * tid + 1];
        sPb1[tid] = pb1[tid];
        sPb2[tid] = pb2[tid];
        sCp[tid]  = dW[tid] * pb3[tid];
    }
    if (tid < 32) {
        sT1a[tid] = tW1[2 * tid];
        sT1b[tid] = tW1[2 * tid + 1];
        sTb1[tid] = tb1[tid];
        sTb2[tid] = tb2[tid];
        sTw3[tid] = tW3[tid];
    }
    __syncthreads();
    if (tid < 64)
        sw[tid] = (sFoldP[0][tid] + sFoldP[1][tid]) + (sFoldP[2][tid] + sFoldP[3][tid]);
    if (tid == 0) {
        float c = 0.0f;
        #pragma unroll
        for (int i = 0; i < 64; ++i) c += sCp[i];
        sScal[0] = c;
        sScal[1] = db[0];
        sScal[2] = tb3[0];
    }
    __syncthreads();

    int warp = tid >> 5, lane = tid & 31;
    int b = blockIdx.x * WARPS_PER_BLOCK + warp;

    float w1a_lo = sW1a[lane],       w1b_lo = sW1b[lane];
    float w1a_hi = sW1a[lane + 32],  w1b_hi = sW1b[lane + 32];
    float b1_lo  = sPb1[lane],       b1_hi  = sPb1[lane + 32];
    float b2_lo  = sPb2[lane],       b2_hi  = sPb2[lane + 32];
    float w_lo   = sw[lane],         w_hi   = sw[lane + 32];
    float cfold = sScal[0], db0 = sScal[1], tb30 = sScal[2];

    float t1 = t[b];
    float h = t1 * (1.0f / (float)NSEG);

    // ---- Per-warp g-grid tabulation: 5 batches of 4 points
    for (int batch = 0; batch < 5; ++batch) {
        int j4 = batch * 4;
        float taus[4];
        #pragma unroll
        for (int s = 0; s < 4; ++s) taus[s] = (float)(j4 + s - 1) * h;

        float h1lo[4], h1hi[4];
        #pragma unroll
        for (int s = 0; s < 4; ++s) {
            h1lo[s] = fast_tanh(fmaf(w1a_lo, t1, fmaf(w1b_lo, taus[s], b1_lo)));
            h1hi[s] = fast_tanh(fmaf(w1a_hi, t1, fmaf(w1b_hi, taus[s], b1_hi)));
        }
        float acc_lo[4], acc_hi[4];
        #pragma unroll
        for (int s = 0; s < 4; ++s) { acc_lo[s] = b2_lo; acc_hi[s] = b2_hi; }

        #pragma unroll 4
        for (int k = 0; k < 32; ++k) {
            float alo[4], ahi[4];
            #pragma unroll
            for (int s = 0; s < 4; ++s) {
                alo[s] = __shfl_sync(0xffffffffu, h1lo[s], k);
                ahi[s] = __shfl_sync(0xffffffffu, h1hi[s], k);
            }
            float wA = sW2T[k * 65 + lane];
            float wB = sW2T[(k + 32) * 65 + lane];
            float wC = sW2T[k * 65 + lane + 32];
            float wD = sW2T[(k + 32) * 65 + lane + 32];
            #pragma unroll
            for (int s = 0; s < 4; ++s) {
                acc_lo[s] = fmaf(wA, alo[s], fmaf(wB, ahi[s], acc_lo[s]));
                acc_hi[s] = fmaf(wC, alo[s], fmaf(wD, ahi[s], acc_hi[s]));
            }
        }
        #pragma unroll
        for (int s = 0; s < 4; ++s) {
            float v = fmaf(w_lo, fast_tanh(acc_lo[s]), w_hi * fast_tanh(acc_hi[s]));
            v = warp_sum(v) + cfold;
            if (lane == 0) sG[warp][j4 + s] = v;
        }
    }
    __syncwarp();
    const float* sGw = sG[warp];

    float ta  = sT1a[lane], tbw = sT1b[lane], tb1r = sTb1[lane];
    float tb2r = sTb2[lane], tw3r = sTw3[lane];

    const float C2 = 0.2f, C3 = 0.3f, C4 = 0.8f, C5 = (float)(8.0 / 9.0);
    const float A21 = 0.2f;
    const float A31 = (float)(3.0 / 40.0),   A32 = (float)(9.0 / 40.0);
    const float A41 = (float)(44.0 / 45.0),  A42 = (float)(-56.0 / 15.0), A43 = (float)(32.0 / 9.0);
    const float A51 = (float)(19372.0 / 6561.0), A52 = (float)(-25360.0 / 2187.0);
    const float A53 = (float)(64448.0 / 6561.0), A54 = (float)(-212.0 / 729.0);
    const float A61 = (float)(9017.0 / 3168.0),  A62 = (float)(-355.0 / 33.0);
    const float A63 = (float)(46732.0 / 5247.0), A64 = (float)(49.0 / 176.0);
    const float A65 = (float)(-5103.0 / 18656.0);
    const float B1 = (float)(35.0 / 384.0), B3 = (float)(500.0 / 1113.0);
    const float B4 = (float)(125.0 / 192.0), B5 = (float)(-2187.0 / 6784.0);
    const float B6 = (float)(11.0 / 84.0);
    const float E1 = (float)(35.0 / 384.0 - 5179.0 / 57600.0);
    const float E3 = (float)(500.0 / 1113.0 - 7571.0 / 16695.0);
    const float E4 = (float)(125.0 / 192.0 - 393.0 / 640.0);
    const float E5 = (float)(-2187.0 / 6784.0 + 92097.0 / 339200.0);
    const float E6 = (float)(11.0 / 84.0 - 187.0 / 2100.0);
    const float E7 = (float)(-1.0 / 40.0);
    const float RTOL = 1e-3f, ATOL = 1e-6f;
    const float SAFETY = 0.9f, FMIN = 0.2f, FMAX = 10.0f;

    float inv_h = __fdividef((float)NSEG, t1);
    float tau = 0.0f, y = 0.0f, dt = 0.01f;

    // FSAL: f1 = theta(tau, y); updated via the f7 hand-off on accept.
    float f1 = theta_eval(tb1r, 0.0f, tbw, tb2r, tw3r, sT2T, lane) + tb30;

    for (int it = 0; it < MAX_STEPS; ++it) {
        float remaining = t1 - tau;
        if (remaining <= 1e-10f) break;
        float dt_eff = fminf(dt, remaining);

        float taus[6];
        taus[0] = tau;
        taus[1] = tau + C2 * dt_eff;
        taus[2] = tau + C3 * dt_eff;
        taus[3] = tau + C4 * dt_eff;
        taus[4] = tau + C5 * dt_eff;
        taus[5] = tau + dt_eff;

        float g[6];
        #pragma unroll
        for (int s = 0; s < 6; ++s) g[s] = g_interp(sGw, taus[s], inv_h);

        float pre[6];
        #pragma unroll
        for (int s = 0; s < 6; ++s) pre[s] = fmaf(ta, taus[s], tb1r);

        float k1 = fmaf(g[0], f1, db0);

        float y2 = fmaf(dt_eff, A21 * k1, y);
        float f2 = theta_eval(pre[1], y2, tbw, tb2r, tw3r, sT2T, lane) + tb30;
        float k2 = fmaf(g[1], f2, db0);

        float y3 = fmaf(dt_eff, fmaf(A31, k1, A32 * k2), y);
        float f3 = theta_eval(pre[2], y3, tbw, tb2r, tw3r, sT2T, lane) + tb30;
        float k3 = fmaf(g[2], f3, db0);

        float y4 = fmaf(dt_eff, fmaf(A41, k1, fmaf(A42, k2, A43 * k3)), y);
        float f4 = theta_eval(pre[3], y4, tbw, tb2r, tw3r, sT2T, lane) + tb30;
        float k4 = fmaf(g[3], f4, db0);

        float y5i = fmaf(dt_eff, fmaf(A51, k1, fmaf(A52, k2, fmaf(A53, k3, A54 * k4))), y);
        float f5 = theta_eval(pre[4], y5i, tbw, tb2r, tw3r, sT2T, lane) + tb30;
        float k5 = fmaf(g[4], f5, db0);

        float y6 = fmaf(dt_eff, fmaf(A61, k1, fmaf(A62, k2, fmaf(A63, k3, fmaf(A64, k4, A65 * k5)))), y);
        float f6 = theta_eval(pre[5], y6, tbw, tb2r, tw3r, sT2T, lane) + tb30;
        float k6 = fmaf(g[5], f6, db0);

        float y5 = fmaf(dt_eff,
                        fmaf(B1, k1, fmaf(B3, k3, fmaf(B4, k4, fmaf(B5, k5, B6 * k6)))),
                        y);
        float f7 = theta_eval(pre[5], y5, tbw, tb2r, tw3r, sT2T, lane) + tb30;
        float k7 = fmaf(g[5], f7, db0);

        float err = dt_eff *
            fmaf(E1, k1, fmaf(E3, k3, fmaf(E4, k4, fmaf(E5, k5, fmaf(E6, k6, E7 * k7)))));
        float scale = fmaf(RTOL, fmaxf(fabsf(y), fabsf(y5)), ATOL);
        float r = __fdividef(err, scale);
        float err_norm = sqrtf(fmaf(r, r, 1e-30f));

        bool accept = (err_norm <= 1.0f);
        float en = fmaxf(err_norm, 1e-10f);
        float factor = SAFETY * exp2f(-0.2f * __log2f(en));
        factor = fminf(fmaxf(factor, FMIN), FMAX);

        if (accept) {
            tau = tau + dt_eff;
            y = y5;
            f1 = f7;   // FSAL hand-off
        }
        dt = fmaxf(dt_eff * factor, 1e-8f);
    }

    if (lane == 0) out[b] = y;
}

extern "C" void kernel_launch(void* const* d_in, const int* in_sizes, int n_in,
                              void* d_out, int out_size) {
    const float* t    = (const float*)d_in[0];
    const float* pW1  = (const float*)d_in[1];
    const float* pb1  = (const float*)d_in[2];
    const float* pW2  = (const float*)d_in[3];
    const float* pb2  = (const float*)d_in[4];
    const float* pW3  = (const float*)d_in[5];
    const float* pb3  = (const float*)d_in[6];
    const float* dW   = (const float*)d_in[7];
    const float* db   = (const float*)d_in[8];
    const float* tW1  = (const float*)d_in[9];
    const float* tb1  = (const float*)d_in[10];
    const float* tW2  = (const float*)d_in[11];
    const float* tb2  = (const float*)d_in[12];
    const float* tW3  = (const float*)d_in[13];
    const float* tb3  = (const float*)d_in[14];
    float* out = (float*)d_out;

    neural_ode_kernel<<<BATCH / WARPS_PER_BLOCK, BLOCK>>>(
        t, pW1, pb1, pW2, pb2, pW3, pb3, dW, db,
        tW1, tb1, tW2, tb2, tW3, tb3, out);
}

// round 9
// speedup vs baseline: 1.3313x; 1.3313x over previous
#include <cuda_runtime.h>
#include <math.h>

#define BATCH 1024
#define WARPS_PER_BLOCK 8
#define BLOCK (WARPS_PER_BLOCK * 32)
#define MAX_STEPS 128

// Grid tabulation of g(t1, tau): NG points, tau_j = (j-1)*h, h = t1/NSEG
#define NG 12
#define NSEG 9
#define NBATCH 3

// Fast warp sum via integer redux (sm_80+). Fixed-point 2^-17 quantization via
// the float magic-number trick. Requires |sum| < 32 (tanh-bounded dot terms).
__device__ __forceinline__ float warp_sum(float v) {
    float biased = fmaf(v, 131072.0f, 12582912.0f);   // v*2^17 + 1.5*2^23
    int xi = __float_as_int(biased) - 0x4B400000;     // round(v*2^17)
    int s;
    asm("redux.sync.add.s32 %0, %1, 0xffffffff;" : "=r"(s) : "r"(xi));
    float fs = __int_as_float(s + 0x4B400000) - 12582912.0f;  // (float)s
    return fs * 7.62939453125e-06f;                   // * 2^-17
}

// Hardware MUFU tanh (sm_75+): ~16 cyc, max abs err ~5e-4
__device__ __forceinline__ float fast_tanh(float x) {
    float r;
    asm("tanh.approx.f32 %0, %1;" : "=f"(r) : "f"(x));
    return r;
}

// theta MLP layer2+3. Weights live in per-lane registers rT2[32] (column
// `lane` of tW2). hv broadcast through smem (1 STS + 8 LDS.128) instead of
// 32 SHFL — MIO ops per eval drop 64 -> ~10.
__device__ __forceinline__ float theta_eval(float pre, float ys, float tbw,
                                            float tb2r, float tw3r,
                                            const float* __restrict__ rT2,
                                            float* __restrict__ hvbuf,
                                            int lane) {
    float hv = fast_tanh(fmaf(tbw, ys, pre));
    hvbuf[lane] = hv;
    __syncwarp();
    const float4* h4p = (const float4*)hvbuf;
    float a0 = tb2r, a1 = 0.0f, a2 = 0.0f, a3 = 0.0f;
    #pragma unroll
    for (int q = 0; q < 8; ++q) {
        float4 h4 = h4p[q];
        a0 = fmaf(rT2[4 * q + 0], h4.x, a0);
        a1 = fmaf(rT2[4 * q + 1], h4.y, a1);
        a2 = fmaf(rT2[4 * q + 2], h4.z, a2);
        a3 = fmaf(rT2[4 * q + 3], h4.w, a3);
    }
    float h2 = fast_tanh((a0 + a1) + (a2 + a3));
    return warp_sum(tw3r * h2);
}

// 4-point Lagrange cubic interpolation of g at tau.
__device__ __forceinline__ float g_interp(const float* __restrict__ sGw,
                                          float tau, float inv_h) {
    float s = fmaf(tau, inv_h, 1.0f);
    float fi = floorf(s);
    int i = (int)fi;
    i = i < 1 ? 1 : (i > NSEG ? NSEG : i);
    float u = s - (float)i;
    float p0 = sGw[i - 1], p1 = sGw[i], p2 = sGw[i + 1], p3 = sGw[i + 2];
    float um1 = u - 1.0f, um2 = u - 2.0f, up1 = u + 1.0f;
    float w0 = (-1.0f / 6.0f) * u * um1 * um2;
    float w1 = 0.5f * up1 * um1 * um2;
    float w2 = -0.5f * up1 * u * um2;
    float w3 = (1.0f / 6.0f) * up1 * u * um1;
    return fmaf(w0, p0, fmaf(w1, p1, fmaf(w2, p2, w3 * p3)));
}

// ---------------------------------------------------------------------------
// Single fused kernel.
// ---------------------------------------------------------------------------
__global__ void __launch_bounds__(BLOCK, 1)
neural_ode_kernel(const float* __restrict__ t,
                  const float* __restrict__ pW1, const float* __restrict__ pb1,
                  const float* __restrict__ pW2, const float* __restrict__ pb2,
                  const float* __restrict__ pW3, const float* __restrict__ pb3,
                  const float* __restrict__ dW, const float* __restrict__ db,
                  const float* __restrict__ tW1, const float* __restrict__ tb1,
                  const float* __restrict__ tW2, const float* __restrict__ tb2,
                  const float* __restrict__ tW3, const float* __restrict__ tb3,
                  float* __restrict__ out) {
    __shared__ float sW2T[64 * 65];   // pW2 transposed, padded (prologue only)
    __shared__ float sT2T[32 * 33];   // tW2 transposed staging
    __shared__ float sW1a[64], sW1b[64], sPb1[64], sPb2[64], sw[64];
    __shared__ float sFoldP[4][64];
    __shared__ float sCp[64];
    __shared__ float sT1a[32], sT1b[32], sTb1[32], sTb2[32], sTw3[32];
    __shared__ float sScal[3];        // c_fold, db0, tb3_0
    __shared__ float sG[WARPS_PER_BLOCK][NG];
    __shared__ __align__(16) float2 sPair[WARPS_PER_BLOCK][2][4][32];
    __shared__ __align__(16) float sHv[WARPS_PER_BLOCK][2][32];

    int tid = threadIdx.x;
    for (int idx = tid; idx < 4096; idx += BLOCK) {
        int j = idx >> 6, k = idx & 63;
        sW2T[k * 65 + j] = pW2[idx];
    }
    for (int idx = tid; idx < 1024; idx += BLOCK) {
        int j = idx >> 5, k = idx & 31;
        sT2T[k * 33 + j] = tW2[idx];
    }
    // Cooperative decoder fold: w_j = sum_i dW[i]*pW3[i][j]
    {
        int q = tid >> 6, j = tid & 63;
        float p = 0.0f;
        #pragma unroll
        for (int i = 0; i < 16; ++i)
            p = fmaf(dW[q * 16 + i], pW3[(q * 16 + i) * 64 + j], p);
        sFoldP[q][j] = p;
    }
    if (tid < 64) {
        sW1a[tid] = pW1[2 * tid];
        sW1b[tid] = pW1[2 * tid + 1];
        sPb1[tid] = pb1[tid];
        sPb2[tid] = pb2[tid];
        sCp[tid]  = dW[tid] * pb3[tid];
    }
    if (tid < 32) {
        sT1a[tid] = tW1[2 * tid];
        sT1b[tid] = tW1[2 * tid + 1];
        sTb1[tid] = tb1[tid];
        sTb2[tid] = tb2[tid];
        sTw3[tid] = tW3[tid];
    }
    __syncthreads();
    if (tid < 64)
        sw[tid] = (sFoldP[0][tid] + sFoldP[1][tid]) + (sFoldP[2][tid] + sFoldP[3][tid]);
    if (tid == 0) {
        float c = 0.0f;
        #pragma unroll
        for (int i = 0; i < 64; ++i) c += sCp[i];
        sScal[0] = c;
        sScal[1] = db[0];
        sScal[2] = tb3[0];
    }
    __syncthreads();

    int warp = tid >> 5, lane = tid & 31;
    int b = blockIdx.x * WARPS_PER_BLOCK + warp;

    // theta layer-2 weight column -> registers (constant-indexed, fully unrolled)
    float rT2[32];
    #pragma unroll
    for (int kk = 0; kk < 32; ++kk) rT2[kk] = sT2T[kk * 33 + lane];

    float w1a_lo = sW1a[lane],       w1b_lo = sW1b[lane];
    float w1a_hi = sW1a[lane + 32],  w1b_hi = sW1b[lane + 32];
    float b1_lo  = sPb1[lane],       b1_hi  = sPb1[lane + 32];
    float b2_lo  = sPb2[lane],       b2_hi  = sPb2[lane + 32];
    float w_lo   = sw[lane],         w_hi   = sw[lane + 32];
    float cfold = sScal[0], db0 = sScal[1], tb30 = sScal[2];

    float t1 = t[b];
    float h = t1 * (1.0f / (float)NSEG);

    // ---- Per-warp g-grid tabulation: NBATCH batches of 4 points.
    // h1 pairs broadcast through smem (4 LDS.64/iter) instead of 8 SHFL/iter.
    for (int batch = 0; batch < NBATCH; ++batch) {
        int j4 = batch * 4;
        int pb = batch & 1;
        float taus[4];
        #pragma unroll
        for (int s = 0; s < 4; ++s) taus[s] = (float)(j4 + s - 1) * h;

        #pragma unroll
        for (int s = 0; s < 4; ++s) {
            float lo = fast_tanh(fmaf(w1a_lo, t1, fmaf(w1b_lo, taus[s], b1_lo)));
            float hi = fast_tanh(fmaf(w1a_hi, t1, fmaf(w1b_hi, taus[s], b1_hi)));
            sPair[warp][pb][s][lane] = make_float2(lo, hi);
        }
        __syncwarp();

        float acc_lo[4], acc_hi[4];
        #pragma unroll
        for (int s = 0; s < 4; ++s) { acc_lo[s] = b2_lo; acc_hi[s] = b2_hi; }

        #pragma unroll 4
        for (int k = 0; k < 32; ++k) {
            float2 p0 = sPair[warp][pb][0][k];
            float2 p1 = sPair[warp][pb][1][k];
            float2 p2 = sPair[warp][pb][2][k];
            float2 p3 = sPair[warp][pb][3][k];
            float wA = sW2T[k * 65 + lane];
            float wB = sW2T[(k + 32) * 65 + lane];
            float wC = sW2T[k * 65 + lane + 32];
            float wD = sW2T[(k + 32) * 65 + lane + 32];
            acc_lo[0] = fmaf(wA, p0.x, fmaf(wB, p0.y, acc_lo[0]));
            acc_hi[0] = fmaf(wC, p0.x, fmaf(wD, p0.y, acc_hi[0]));
            acc_lo[1] = fmaf(wA, p1.x, fmaf(wB, p1.y, acc_lo[1]));
            acc_hi[1] = fmaf(wC, p1.x, fmaf(wD, p1.y, acc_hi[1]));
            acc_lo[2] = fmaf(wA, p2.x, fmaf(wB, p2.y, acc_lo[2]));
            acc_hi[2] = fmaf(wC, p2.x, fmaf(wD, p2.y, acc_hi[2]));
            acc_lo[3] = fmaf(wA, p3.x, fmaf(wB, p3.y, acc_lo[3]));
            acc_hi[3] = fmaf(wC, p3.x, fmaf(wD, p3.y, acc_hi[3]));
        }
        #pragma unroll
        for (int s = 0; s < 4; ++s) {
            float v = fmaf(w_lo, fast_tanh(acc_lo[s]), w_hi * fast_tanh(acc_hi[s]));
            v = warp_sum(v) + cfold;
            if (lane == 0) sG[warp][j4 + s] = v;
        }
        __syncwarp();
    }
    const float* sGw = sG[warp];

    float ta  = sT1a[lane], tbw = sT1b[lane], tb1r = sTb1[lane];
    float tb2r = sTb2[lane], tw3r = sTw3[lane];

    const float C2 = 0.2f, C3 = 0.3f, C4 = 0.8f, C5 = (float)(8.0 / 9.0);
    const float A21 = 0.2f;
    const float A31 = (float)(3.0 / 40.0),   A32 = (float)(9.0 / 40.0);
    const float A41 = (float)(44.0 / 45.0),  A42 = (float)(-56.0 / 15.0), A43 = (float)(32.0 / 9.0);
    const float A51 = (float)(19372.0 / 6561.0), A52 = (float)(-25360.0 / 2187.0);
    const float A53 = (float)(64448.0 / 6561.0), A54 = (float)(-212.0 / 729.0);
    const float A61 = (float)(9017.0 / 3168.0),  A62 = (float)(-355.0 / 33.0);
    const float A63 = (float)(46732.0 / 5247.0), A64 = (float)(49.0 / 176.0);
    const float A65 = (float)(-5103.0 / 18656.0);
    const float B1 = (float)(35.0 / 384.0), B3 = (float)(500.0 / 1113.0);
    const float B4 = (float)(125.0 / 192.0), B5 = (float)(-2187.0 / 6784.0);
    const float B6 = (float)(11.0 / 84.0);
    const float E1 = (float)(35.0 / 384.0 - 5179.0 / 57600.0);
    const float E3 = (float)(500.0 / 1113.0 - 7571.0 / 16695.0);
    const float E4 = (float)(125.0 / 192.0 - 393.0 / 640.0);
    const float E5 = (float)(-2187.0 / 6784.0 + 92097.0 / 339200.0);
    const float E6 = (float)(11.0 / 84.0 - 187.0 / 2100.0);
    const float E7 = (float)(-1.0 / 40.0);
    const float RTOL = 1e-3f, ATOL = 1e-6f;
    const float SAFETY = 0.9f, FMIN = 0.2f, FMAX = 10.0f;

    float inv_h = __fdividef((float)NSEG, t1);
    float tau = 0.0f, y = 0.0f, dt = 0.01f;

    int tb = 0;  // double-buffer parity for hv broadcasts

    // FSAL: f1 = theta(tau, y); updated via the f7 hand-off on accept.
    float f1 = theta_eval(tb1r, 0.0f, tbw, tb2r, tw3r, rT2, sHv[warp][tb], lane) + tb30;

    for (int it = 0; it < MAX_STEPS; ++it) {
        float remaining = t1 - tau;
        if (remaining <= 1e-10f) break;
        float dt_eff = fminf(dt, remaining);

        float taus[6];
        taus[0] = tau;
        taus[1] = tau + C2 * dt_eff;
        taus[2] = tau + C3 * dt_eff;
        taus[3] = tau + C4 * dt_eff;
        taus[4] = tau + C5 * dt_eff;
        taus[5] = tau + dt_eff;

        float g[6];
        #pragma unroll
        for (int s = 0; s < 6; ++s) g[s] = g_interp(sGw, taus[s], inv_h);

        float pre[6];
        #pragma unroll
        for (int s = 0; s < 6; ++s) pre[s] = fmaf(ta, taus[s], tb1r);

        float k1 = fmaf(g[0], f1, db0);

        float y2 = fmaf(dt_eff, A21 * k1, y);
        tb ^= 1;
        float f2 = theta_eval(pre[1], y2, tbw, tb2r, tw3r, rT2, sHv[warp][tb], lane) + tb30;
        float k2 = fmaf(g[1], f2, db0);

        float y3 = fmaf(dt_eff, fmaf(A31, k1, A32 * k2), y);
        tb ^= 1;
        float f3 = theta_eval(pre[2], y3, tbw, tb2r, tw3r, rT2, sHv[warp][tb], lane) + tb30;
        float k3 = fmaf(g[2], f3, db0);

        float y4 = fmaf(dt_eff, fmaf(A41, k1, fmaf(A42, k2, A43 * k3)), y);
        tb ^= 1;
        float f4 = theta_eval(pre[3], y4, tbw, tb2r, tw3r, rT2, sHv[warp][tb], lane) + tb30;
        float k4 = fmaf(g[3], f4, db0);

        float y5i = fmaf(dt_eff, fmaf(A51, k1, fmaf(A52, k2, fmaf(A53, k3, A54 * k4))), y);
        tb ^= 1;
        float f5 = theta_eval(pre[4], y5i, tbw, tb2r, tw3r, rT2, sHv[warp][tb], lane) + tb30;
        float k5 = fmaf(g[4], f5, db0);

        float y6 = fmaf(dt_eff, fmaf(A61, k1, fmaf(A62, k2, fmaf(A63, k3, fmaf(A64, k4, A65 * k5)))), y);
        tb ^= 1;
        float f6 = theta_eval(pre[5], y6, tbw, tb2r, tw3r, rT2, sHv[warp][tb], lane) + tb30;
        float k6 = fmaf(g[5], f6, db0);

        float y5 = fmaf(dt_eff,
                        fmaf(B1, k1, fmaf(B3, k3, fmaf(B4, k4, fmaf(B5, k5, B6 * k6)))),
                        y);
        tb ^= 1;
        float f7 = theta_eval(pre[5], y5, tbw, tb2r, tw3r, rT2, sHv[warp][tb], lane) + tb30;
        float k7 = fmaf(g[5], f7, db0);

        float err = dt_eff *
            fmaf(E1, k1, fmaf(E3, k3, fmaf(E4, k4, fmaf(E5, k5, fmaf(E6, k6, E7 * k7)))));
        float scale = fmaf(RTOL, fmaxf(fabsf(y), fabsf(y5)), ATOL);
        float r = __fdividef(err, scale);
        float err_norm = sqrtf(fmaf(r, r, 1e-30f));

        bool accept = (err_norm <= 1.0f);
        float en = fmaxf(err_norm, 1e-10f);
        float factor = SAFETY * exp2f(-0.2f * __log2f(en));
        factor = fminf(fmaxf(factor, FMIN), FMAX);

        if (accept) {
            tau = tau + dt_eff;
            y = y5;
            f1 = f7;   // FSAL hand-off
        }
        dt = fmaxf(dt_eff * factor, 1e-8f);
    }

    if (lane == 0) out[b] = y;
}

extern "C" void kernel_launch(void* const* d_in, const int* in_sizes, int n_in,
                              void* d_out, int out_size) {
    const float* t    = (const float*)d_in[0];
    const float* pW1  = (const float*)d_in[1];
    const float* pb1  = (const float*)d_in[2];
    const float* pW2  = (const float*)d_in[3];
    const float* pb2  = (const float*)d_in[4];
    const float* pW3  = (const float*)d_in[5];
    const float* pb3  = (const float*)d_in[6];
    const float* dW   = (const float*)d_in[7];
    const float* db   = (const float*)d_in[8];
    const float* tW1  = (const float*)d_in[9];
    const float* tb1  = (const float*)d_in[10];
    const float* tW2  = (const float*)d_in[11];
    const float* tb2  = (const float*)d_in[12];
    const float* tW3  = (const float*)d_in[13];
    const float* tb3  = (const float*)d_in[14];
    float* out = (float*)d_out;

    neural_ode_kernel<<<BATCH / WARPS_PER_BLOCK, BLOCK>>>(
        t, pW1, pb1, pW2, pb2, pW3, pb3, dW, db,
        tW1, tb1, tW2, tb2, tW3, tb3, out);
}